// round 6
// baseline (speedup 1.0000x reference)
#include <cuda_runtime.h>
#include <cstdint>

#define NB 128
#define NT 1024
#define BB 16
#define TT 1024
#define DD 1024
#define SS 512
#define MM 16
#define KSPLIT 8
#define KB_LEN 384               // k per block
#define CBF 1540                 // floats per cb region (6160 B, bank-offset pad)

// ---------------- persistent state (device globals; no allocation) ----------
__device__ float g_h[BB * DD];
__device__ float g_c[BB * DD];
__device__ float g_ctx[BB * DD];
__device__ float g_gpart[KSPLIT][BB][4 * DD];   // 2 MB
__device__ float g_watt[BB][SS];
__device__ unsigned g_count;
__device__ volatile unsigned g_gen;

__device__ __forceinline__ float sigf(float x) {
    return __fdividef(1.0f, 1.0f + __expf(-x));
}
__device__ __forceinline__ float tanhfast(float x) {
    const float xc = fminf(fmaxf(x, -15.0f), 15.0f);
    const float e  = __expf(2.0f * xc);
    return __fdividef(e - 1.0f, e + 1.0f);
}

__device__ __forceinline__ void grid_barrier() {
    __syncthreads();
    if (threadIdx.x == 0) {
        unsigned gen = g_gen;
        __threadfence();
        unsigned arrived = atomicAdd(&g_count, 1u);
        if (arrived == NB - 1) {
            g_count = 0u;
            __threadfence();
            g_gen = gen + 1u;
        } else {
            while (g_gen == gen) { __nanosleep(20); }
            __threadfence();
        }
    }
    __syncthreads();
}

extern __shared__ float smem[];  // 48 KB dynamic only

__device__ __forceinline__ uint32_t swz(uint32_t L) {
    return L ^ ((L >> 3) & 0x70u);
}

__global__ __launch_bounds__(NT, 1) void tts_kernel(
    const float* __restrict__ x_in,    // [B,T,D]
    const float* __restrict__ memv,    // [B,S,D]
    const int*   __restrict__ lens,    // [B]
    const float* __restrict__ W_ih,    // [4096,2048]
    const float* __restrict__ W_hh,    // [4096,1024]
    const float* __restrict__ b_ih,    // [4096]
    const float* __restrict__ b_hh,    // [4096]
    const float* __restrict__ Wg_w,    // [48,1024]
    const float* __restrict__ Wg_b,    // [48]
    float* __restrict__ out)
{
    const int bid = blockIdx.x;
    const int tid = threadIdx.x;

    // smem layout (floats): x staging [0, 4*CBF) = 6160; then scratch
    float* sh_phi   = smem + 6160;   // 48
    float* sh_ksi   = smem + 6208;   // 16
    float* sh_binv  = smem + 6224;   // 16
    float* sh_alpha = smem + 6240;   // 16
    float* sh_h     = smem + 6272;   // 1024

    float* out_ctx   = out;
    float* out_align = out + BB * DD;
    float* out_term  = out + BB * DD + (size_t)BB * TT * SS;

    for (int i = bid * NT + tid; i < BB * DD; i += NB * NT) {
        g_h[i] = 0.0f; g_c[i] = 0.0f; g_ctx[i] = 0.0f;
    }
    grid_barrier();

    // mapping: 16 j-tiles (256 j) x 8 k-splits (384 k)
    const int jt = bid >> 3;            // 0..15
    const int kb = bid & 7;             // 0..7
    const int kbase = kb * KB_LEN;

    // warp covers 8 rows; lane = bg(b0) | ksl(b1-2) | jsub(b3-4)
    const int w     = tid >> 5;
    const int lane  = tid & 31;
    const int bg    = lane & 1;
    const int ksl   = (lane >> 1) & 3;
    const int jsub  = (lane >> 3) & 3;
    const int j0    = jt * 256 + w * 8 + jsub * 2;   // rows j0, j0+1
    const int ksl96 = ksl * 96;

    const float* wih = W_ih + (size_t)j0 * 2048;
    const float* whh = W_hh + (size_t)j0 * 1024;

    for (int t = 0; t < TT; ++t) {
        // ============ stage x slice [16 b x 384 k] into smem (swizzled) ====
        #pragma unroll
        for (int r = 0; r < 6; ++r) {
            const int idx = r * NT + tid;        // < 6144
            const int b   = idx / KB_LEN;
            const int kl  = idx - b * KB_LEN;
            const int k   = kbase + kl;
            float v;
            if (k < DD)            v = x_in[((size_t)b * TT + t) * DD + k];
            else if (k < 2 * DD)   v = g_ctx[b * DD + (k - DD)];
            else                   v = g_h[b * DD + (k - 2 * DD)];
            const int cb = b >> 2, bl = b & 3;
            const uint32_t L = swz((uint32_t)(kl * 16 + bl * 4));
            *reinterpret_cast<float*>(
                reinterpret_cast<char*>(smem) + cb * (CBF * 4) + L) = v;
        }
        __syncthreads();

        // ======= gates GEMM: 2 rows x 4 pairs, prefetch, packed f32x2 ======
        {
            unsigned long long acc[2][4];
            #pragma unroll
            for (int a = 0; a < 2; ++a)
                #pragma unroll
                for (int p = 0; p < 4; ++p) acc[a][p] = 0ull;

            float4 wc[2], wn[2];

            auto ldw = [&](float4* dst, int i) {
                const int kq = kbase + ksl96 + i * 4;
                if (kq < 2048) {
                    const float* p = wih + kq;
                    dst[0] = *reinterpret_cast<const float4*>(p);
                    dst[1] = *reinterpret_cast<const float4*>(p + 2048);
                } else {
                    const float* p = whh + (kq - 2048);
                    dst[0] = *reinterpret_cast<const float4*>(p);
                    dst[1] = *reinterpret_cast<const float4*>(p + 1024);
                }
            };

            ldw(wc, 0);
            const char* xb = reinterpret_cast<const char*>(smem)
                           + (bg * 2) * (CBF * 4);

            #pragma unroll 2
            for (int i = 0; i < 24; ++i) {
                if (i < 23) ldw(wn, i + 1);
                const int klb = ksl96 + i * 4;
                #pragma unroll
                for (int q = 0; q < 4; ++q) {
                    const uint32_t L = swz((uint32_t)((klb + q) * 16));
                    const double2 d0 = *reinterpret_cast<const double2*>(xb + L);
                    const double2 d1 = *reinterpret_cast<const double2*>(xb + CBF * 4 + L);
                    const unsigned long long xv0 = __double_as_longlong(d0.x);
                    const unsigned long long xv1 = __double_as_longlong(d0.y);
                    const unsigned long long xv2 = __double_as_longlong(d1.x);
                    const unsigned long long xv3 = __double_as_longlong(d1.y);
                    #pragma unroll
                    for (int a = 0; a < 2; ++a) {
                        const float wv = (q == 0) ? wc[a].x : (q == 1) ? wc[a].y
                                       : (q == 2) ? wc[a].z : wc[a].w;
                        unsigned long long w2;
                        asm("mov.b64 %0, {%1, %1};" : "=l"(w2) : "r"(__float_as_uint(wv)));
                        asm("fma.rn.f32x2 %0, %1, %2, %0;" : "+l"(acc[a][0]) : "l"(w2), "l"(xv0));
                        asm("fma.rn.f32x2 %0, %1, %2, %0;" : "+l"(acc[a][1]) : "l"(w2), "l"(xv1));
                        asm("fma.rn.f32x2 %0, %1, %2, %0;" : "+l"(acc[a][2]) : "l"(w2), "l"(xv2));
                        asm("fma.rn.f32x2 %0, %1, %2, %0;" : "+l"(acc[a][3]) : "l"(w2), "l"(xv3));
                    }
                }
                wc[0] = wn[0];
                wc[1] = wn[1];
            }

            // reduce over ksl (lane bits 1-2): xor offsets 2, 4
            #pragma unroll
            for (int off = 2; off <= 4; off <<= 1) {
                #pragma unroll
                for (int a = 0; a < 2; ++a)
                    #pragma unroll
                    for (int p = 0; p < 4; ++p) {
                        unsigned lo = (unsigned)acc[a][p];
                        unsigned hi = (unsigned)(acc[a][p] >> 32);
                        lo = __shfl_xor_sync(0xFFFFFFFFu, lo, off);
                        hi = __shfl_xor_sync(0xFFFFFFFFu, hi, off);
                        unsigned long long o = ((unsigned long long)hi << 32) | lo;
                        asm("add.rn.f32x2 %0, %0, %1;" : "+l"(acc[a][p]) : "l"(o));
                    }
            }

            // lane (bg,ksl): writes row a = ksl&1, pairs p in {2*(ksl>>1), +1}
            const int arow = ksl & 1;
            const int ph   = ksl >> 1;
            #pragma unroll
            for (int a = 0; a < 2; ++a) {
                #pragma unroll
                for (int p = 0; p < 4; ++p) {
                    if (a == arow && (p >> 1) == ph) {
                        const int j  = j0 + a;
                        const int b0 = bg * 8 + 2 * p;
                        const unsigned long long v = acc[a][p];
                        g_gpart[kb][b0][j]     = __uint_as_float((unsigned)v);
                        g_gpart[kb][b0 + 1][j] = __uint_as_float((unsigned)(v >> 32));
                    }
                }
            }
        }
        grid_barrier();  // B1: gates done

        // ============ LSTM + phi + GMM attention (blocks 0..15) ============
        if (bid < BB) {
            const int b = bid;
            {
                const int dd = tid;   // NT == DD
                float gi = b_ih[dd]          + b_hh[dd];
                float gf = b_ih[DD + dd]     + b_hh[DD + dd];
                float gg = b_ih[2 * DD + dd] + b_hh[2 * DD + dd];
                float go = b_ih[3 * DD + dd] + b_hh[3 * DD + dd];
                #pragma unroll
                for (int q = 0; q < KSPLIT; ++q) {
                    gi += g_gpart[q][b][dd];
                    gf += g_gpart[q][b][DD + dd];
                    gg += g_gpart[q][b][2 * DD + dd];
                    go += g_gpart[q][b][3 * DD + dd];
                }
                const float c = sigf(gf) * g_c[b * DD + dd] + sigf(gi) * tanhfast(gg);
                const float h = sigf(go) * tanhfast(c);
                g_c[b * DD + dd] = c;
                g_h[b * DD + dd] = h;
                sh_h[dd] = h;
            }
            __syncthreads();

            // phi = h @ Wg_w^T + Wg_b
            {
                const int wq = tid >> 5, lane5 = tid & 31;
                for (int mm = wq; mm < 3 * MM; mm += 32) {
                    const float* wr = Wg_w + (size_t)mm * DD;
                    float acc = 0.0f;
                    #pragma unroll
                    for (int i = 0; i < 32; ++i)
                        acc += wr[i * 32 + lane5] * sh_h[i * 32 + lane5];
                    #pragma unroll
                    for (int off = 16; off; off >>= 1)
                        acc += __shfl_xor_sync(0xFFFFFFFFu, acc, off);
                    if (lane5 == 0) sh_phi[mm] = acc + Wg_b[mm];
                }
            }
            __syncthreads();

            if (tid < 32) {
                const int m = tid & 15;
                const float pk = sh_phi[m];
                const float pb = sh_phi[MM + m];
                const float pa = sh_phi[2 * MM + m];
                float mx = pa;
                #pragma unroll
                for (int off = 1; off < 16; off <<= 1)
                    mx = fmaxf(mx, __shfl_xor_sync(0xFFFFFFFFu, mx, off, 16));
                const float e = __expf(pa - mx);
                float sum = e;
                #pragma unroll
                for (int off = 1; off < 16; off <<= 1)
                    sum += __shfl_xor_sync(0xFFFFFFFFu, sum, off, 16);
                if (tid < 16) {
                    sh_alpha[m] = e / sum;
                    sh_ksi[m]   = __expf(pk);
                    sh_binv[m]  = __expf(-pb);
                }
            }
            __syncthreads();

            if (tid < SS) {
                const int s = tid;
                const int lb = lens[b];
                const float fs = (float)s;
                float aw = 0.0f, ar = 0.0f;
                #pragma unroll
                for (int m = 0; m < MM; ++m) {
                    const float binv = sh_binv[m];
                    const float z  = (fs - sh_ksi[m]) * binv;
                    const float hb = 0.5f * binv;
                    const float fr = sigf(z + hb);
                    const float fl = sigf(z - hb);
                    const float al = sh_alpha[m];
                    aw += al * (fr - fl);
                    ar += al * fr;
                }
                g_watt[b][s] = aw;
                out_align[((size_t)b * TT + t) * SS + s] = aw;
                if (t == TT - 1 && s == lb - 1) out_term[b] = 1.0f - ar;
            }
        }
        grid_barrier();  // B2: h, w ready

        // ===================== ctx = w @ memory ============================
        {
            const int b  = bid >> 3;
            const int d0 = (bid & 7) * 128;
            const int wq = tid >> 5, lane5 = tid & 31;
            const float* mb = memv + (size_t)b * SS * DD + d0 + lane5 * 4;
            float4 acc = make_float4(0.f, 0.f, 0.f, 0.f);
            const int sbase = wq * 16;
            #pragma unroll 4
            for (int si = 0; si < 16; ++si) {
                const int s = sbase + si;
                const float wv = g_watt[b][s];
                const float4 mv = *reinterpret_cast<const float4*>(mb + (size_t)s * DD);
                acc.x += wv * mv.x; acc.y += wv * mv.y;
                acc.z += wv * mv.z; acc.w += wv * mv.w;
            }
            float4* red = reinterpret_cast<float4*>(smem);
            red[wq * 32 + lane5] = acc;
            __syncthreads();
            if (tid < 32) {
                float4 r = red[tid];
                #pragma unroll
                for (int q = 1; q < 32; ++q) {
                    const float4 v = red[q * 32 + tid];
                    r.x += v.x; r.y += v.y; r.z += v.z; r.w += v.w;
                }
                const int di = d0 + tid * 4;
                *reinterpret_cast<float4*>(&g_ctx[b * DD + di]) = r;
                if (t == TT - 1)
                    *reinterpret_cast<float4*>(&out_ctx[b * DD + di]) = r;
            }
        }
        grid_barrier();  // B3: ctx ready
    }
}

extern "C" void kernel_launch(void* const* d_in, const int* in_sizes, int n_in,
                              void* d_out, int out_size) {
    (void)in_sizes; (void)n_in; (void)out_size;
    const float* x_in  = (const float*)d_in[0];
    const float* memv  = (const float*)d_in[1];
    const int*   lens  = (const int*)  d_in[2];
    const float* W_ih  = (const float*)d_in[3];
    const float* W_hh  = (const float*)d_in[4];
    const float* b_ih  = (const float*)d_in[5];
    const float* b_hh  = (const float*)d_in[6];
    const float* Wg_w  = (const float*)d_in[7];
    const float* Wg_b  = (const float*)d_in[8];
    tts_kernel<<<NB, NT, 49152>>>(x_in, memv, lens, W_ih, W_hh,
                                  b_ih, b_hh, Wg_w, Wg_b, (float*)d_out);
}

// round 7
// speedup vs baseline: 1.6527x; 1.6527x over previous
#include <cuda_runtime.h>
#include <cstdint>

#define NB 128
#define NT 512
#define BB 16
#define TT 1024
#define DD 1024
#define SS 512
#define MM 16

// ---------------- persistent state (device globals; no allocation) ----------
__device__ float g_h[BB * DD];
__device__ float g_c[BB * DD];
__device__ float g_ctx[BB * DD];
__device__ float g_gpart[4][BB][4 * DD];   // k-split partial gates, 1 MB
__device__ float g_watt[BB][SS];
__device__ unsigned g_count;               // zero-initialized
__device__ int g_flags[NB * 8];            // per-block release flags (32B apart)

__device__ __forceinline__ float sigf(float x) {
    return __fdividef(1.0f, 1.0f + __expf(-x));
}
__device__ __forceinline__ float tanhfast(float x) {
    const float xc = fminf(fmaxf(x, -15.0f), 15.0f);
    const float e  = __expf(2.0f * xc);
    return __fdividef(e - 1.0f, e + 1.0f);
}

// Software grid barrier with DISTRIBUTED release (each block polls its own
// flag line -> no same-address LTS contention on release).
// Grid = 128 blocks <= 148 SMs => single wave, all co-resident.
__device__ __forceinline__ void grid_barrier(int gen) {
    __syncthreads();
    if (threadIdx.x == 0) {
        __threadfence();
        const unsigned arrived = atomicAdd(&g_count, 1u);
        if (arrived == NB - 1) {
            g_count = 0u;
            __threadfence();
            #pragma unroll 8
            for (int i = 0; i < NB; ++i) g_flags[i * 8] = gen;
        } else {
            volatile int* f = &g_flags[blockIdx.x * 8];
            while (*f != gen) { __nanosleep(16); }
        }
        __threadfence();
    }
    __syncthreads();
}

extern __shared__ float smem[];  // 12288 floats = 48 KB dynamic only

__device__ __forceinline__ uint32_t swz(uint32_t L) {
    return L ^ ((L >> 3) & 0x70u);
}

__global__ __launch_bounds__(NT, 1) void tts_kernel(
    const float* __restrict__ x_in,    // [B,T,D]
    const float* __restrict__ memv,    // [B,S,D]
    const int*   __restrict__ lens,    // [B]
    const float* __restrict__ W_ih,    // [4096,2048]
    const float* __restrict__ W_hh,    // [4096,1024]
    const float* __restrict__ b_ih,    // [4096]
    const float* __restrict__ b_hh,    // [4096]
    const float* __restrict__ Wg_w,    // [48,1024]
    const float* __restrict__ Wg_b,    // [48]
    float* __restrict__ out)
{
    const int bid = blockIdx.x;
    const int tid = threadIdx.x;

    // phase-disjoint small scratch carved from dynamic smem
    float* sh_phi   = smem;        // 48 floats
    float* sh_ksi   = smem + 48;   // 16
    float* sh_binv  = smem + 64;   // 16
    float* sh_alpha = smem + 80;   // 16

    float* out_ctx   = out;                                  // [B,1,D]
    float* out_align = out + BB * DD;                        // [B,T,S]
    float* out_term  = out + BB * DD + (size_t)BB * TT * SS; // [B,1]

    int bgen = 0;

    // ------- init state -------
    for (int i = bid * NT + tid; i < BB * DD; i += NB * NT) {
        g_h[i] = 0.0f; g_c[i] = 0.0f; g_ctx[i] = 0.0f;
    }
    grid_barrier(++bgen);

    // gates GEMM mapping: 32 j-tiles x 4 k-splits
    const int jt = bid >> 2;            // 0..31 -> 128 j's each
    const int kb = bid & 3;             // 0..3  -> 768 k's each
    const int kbase = kb * 768;

    // within block: 32 j-groups (4 rows) x [2 batch-groups x 8 k-slices]
    const int lane4 = tid & 15;
    const int bg    = lane4 & 1;        // batches bg*8 .. bg*8+7
    const int ksl   = lane4 >> 1;       // 0..7 k-slice (24 quads each)
    const int j0t   = jt * 128 + (tid >> 4) * 4;

    const float* wih = W_ih + (size_t)j0t * 2048;
    const float* whh = W_hh + (size_t)j0t * 1024;

    for (int t = 0; t < TT; ++t) {
        // ========== stage x slice into smem (swizzled, float4 loads) =======
        // 16 b x 192 quads = 3072 quads, 6 per thread
        #pragma unroll
        for (int r = 0; r < 6; ++r) {
            const int qi = r * NT + tid;         // < 3072
            const int b  = qi / 192;
            const int kq = qi - b * 192;
            const int k  = kbase + kq * 4;
            float4 v;
            if (k < DD)
                v = *reinterpret_cast<const float4*>(&x_in[((size_t)b * TT + t) * DD + k]);
            else if (k < 2 * DD)
                v = *reinterpret_cast<const float4*>(&g_ctx[b * DD + (k - DD)]);
            else
                v = *reinterpret_cast<const float4*>(&g_h[b * DD + (k - 2 * DD)]);
            const int cb = b >> 2, bl = b & 3;
            char* base = reinterpret_cast<char*>(smem) + cb * 12288;
            const int kl = kq * 4;
            *reinterpret_cast<float*>(base + swz((uint32_t)((kl + 0) * 16 + bl * 4))) = v.x;
            *reinterpret_cast<float*>(base + swz((uint32_t)((kl + 1) * 16 + bl * 4))) = v.y;
            *reinterpret_cast<float*>(base + swz((uint32_t)((kl + 2) * 16 + bl * 4))) = v.z;
            *reinterpret_cast<float*>(base + swz((uint32_t)((kl + 3) * 16 + bl * 4))) = v.w;
        }
        __syncthreads();

        // ======= gates GEMM: float4 weights, prefetch, packed f32x2 =======
        {
            unsigned long long acc[4][4];
            #pragma unroll
            for (int a = 0; a < 4; ++a)
                #pragma unroll
                for (int p = 0; p < 4; ++p) acc[a][p] = 0ull;

            float4 wc[4], wn[4];

            auto ldw = [&](float4* dst, int i) {
                const int off = (i * 8 + ksl) * 4;   // 0..767
                const int k = kbase + off;
                if (k < 2048) {
                    const float* p = wih + k;
                    #pragma unroll
                    for (int a = 0; a < 4; ++a)
                        dst[a] = *reinterpret_cast<const float4*>(p + (size_t)a * 2048);
                } else {
                    const float* p = whh + (k - 2048);
                    #pragma unroll
                    for (int a = 0; a < 4; ++a)
                        dst[a] = *reinterpret_cast<const float4*>(p + (size_t)a * 1024);
                }
            };

            ldw(wc, 0);
            const char* xb = reinterpret_cast<const char*>(smem) + (bg * 2) * 12288;

            #pragma unroll 2
            for (int i = 0; i < 24; ++i) {
                if (i < 23) ldw(wn, i + 1);
                const int klb = (i * 8 + ksl) * 4;
                #pragma unroll
                for (int q = 0; q < 4; ++q) {
                    const uint32_t L = swz((uint32_t)((klb + q) * 16));
                    const double2 d0 = *reinterpret_cast<const double2*>(xb + L);
                    const double2 d1 = *reinterpret_cast<const double2*>(xb + 12288 + L);
                    const unsigned long long xv0 = __double_as_longlong(d0.x);
                    const unsigned long long xv1 = __double_as_longlong(d0.y);
                    const unsigned long long xv2 = __double_as_longlong(d1.x);
                    const unsigned long long xv3 = __double_as_longlong(d1.y);
                    #pragma unroll
                    for (int a = 0; a < 4; ++a) {
                        const float wv = (q == 0) ? wc[a].x : (q == 1) ? wc[a].y
                                       : (q == 2) ? wc[a].z : wc[a].w;
                        unsigned long long w2;
                        asm("mov.b64 %0, {%1, %1};" : "=l"(w2) : "r"(__float_as_uint(wv)));
                        asm("fma.rn.f32x2 %0, %1, %2, %0;" : "+l"(acc[a][0]) : "l"(w2), "l"(xv0));
                        asm("fma.rn.f32x2 %0, %1, %2, %0;" : "+l"(acc[a][1]) : "l"(w2), "l"(xv1));
                        asm("fma.rn.f32x2 %0, %1, %2, %0;" : "+l"(acc[a][2]) : "l"(w2), "l"(xv2));
                        asm("fma.rn.f32x2 %0, %1, %2, %0;" : "+l"(acc[a][3]) : "l"(w2), "l"(xv3));
                    }
                }
                #pragma unroll
                for (int a = 0; a < 4; ++a) wc[a] = wn[a];
            }

            // reduce over the 8 k-slices (xor offsets 2,4,8; bg bit preserved)
            #pragma unroll
            for (int off = 2; off <= 8; off <<= 1) {
                #pragma unroll
                for (int a = 0; a < 4; ++a)
                    #pragma unroll
                    for (int p = 0; p < 4; ++p) {
                        unsigned lo = (unsigned)acc[a][p];
                        unsigned hi = (unsigned)(acc[a][p] >> 32);
                        lo = __shfl_xor_sync(0xFFFFFFFFu, lo, off);
                        hi = __shfl_xor_sync(0xFFFFFFFFu, hi, off);
                        unsigned long long o = ((unsigned long long)hi << 32) | lo;
                        asm("add.rn.f32x2 %0, %0, %1;" : "+l"(acc[a][p]) : "l"(o));
                    }
            }

            // lane (bg,ksl): row a = ksl>>1, pairs p with p>>1 == (ksl&1)
            const int arow = ksl >> 1;
            const int psel = ksl & 1;
            #pragma unroll
            for (int a = 0; a < 4; ++a) {
                #pragma unroll
                for (int p = 0; p < 4; ++p) {
                    if (a == arow && (p >> 1) == psel) {
                        const int j = j0t + a;
                        const int b0 = bg * 8 + 2 * p;
                        const unsigned long long v = acc[a][p];
                        g_gpart[kb][b0][j]     = __uint_as_float((unsigned)v);
                        g_gpart[kb][b0 + 1][j] = __uint_as_float((unsigned)(v >> 32));
                    }
                }
            }
        }
        grid_barrier(++bgen);  // B1: gates done

        // ============ LSTM + phi + GMM attention (blocks 0..15) ============
        if (bid < BB) {
            const int b = bid;
            #pragma unroll
            for (int r = 0; r < 2; ++r) {
                const int dd = r * NT + tid;
                float gi = b_ih[dd]          + b_hh[dd];
                float gf = b_ih[DD + dd]     + b_hh[DD + dd];
                float gg = b_ih[2 * DD + dd] + b_hh[2 * DD + dd];
                float go = b_ih[3 * DD + dd] + b_hh[3 * DD + dd];
                #pragma unroll
                for (int q = 0; q < 4; ++q) {
                    gi += g_gpart[q][b][dd];
                    gf += g_gpart[q][b][DD + dd];
                    gg += g_gpart[q][b][2 * DD + dd];
                    go += g_gpart[q][b][3 * DD + dd];
                }
                const float c = sigf(gf) * g_c[b * DD + dd] + sigf(gi) * tanhfast(gg);
                const float h = sigf(go) * tanhfast(c);
                g_c[b * DD + dd] = c;
                g_h[b * DD + dd] = h;
            }
            __syncthreads();

            // phi = h @ Wg_w^T + Wg_b  (48 dots of 1024; warp w -> 3 rows)
            {
                const int w = tid >> 5, lane = tid & 31;
                float hreg[32];
                #pragma unroll
                for (int i = 0; i < 32; ++i) hreg[i] = g_h[b * DD + i * 32 + lane];
                #pragma unroll
                for (int mi = 0; mi < 3; ++mi) {
                    const int mm = w * 3 + mi;
                    const float* wr = Wg_w + (size_t)mm * DD;
                    float acc = 0.0f;
                    #pragma unroll
                    for (int i = 0; i < 32; ++i) acc += wr[i * 32 + lane] * hreg[i];
                    #pragma unroll
                    for (int off = 16; off; off >>= 1)
                        acc += __shfl_xor_sync(0xFFFFFFFFu, acc, off);
                    if (lane == 0) sh_phi[mm] = acc + Wg_b[mm];
                }
            }
            __syncthreads();

            if (tid < 32) {
                const int m = tid & 15;
                const float pk = sh_phi[m];
                const float pb = sh_phi[MM + m];
                const float pa = sh_phi[2 * MM + m];
                float mx = pa;
                #pragma unroll
                for (int off = 1; off < 16; off <<= 1)
                    mx = fmaxf(mx, __shfl_xor_sync(0xFFFFFFFFu, mx, off, 16));
                const float e = __expf(pa - mx);
                float sum = e;
                #pragma unroll
                for (int off = 1; off < 16; off <<= 1)
                    sum += __shfl_xor_sync(0xFFFFFFFFu, sum, off, 16);
                if (tid < 16) {
                    sh_alpha[m] = e / sum;
                    sh_ksi[m]   = __expf(pk);
                    sh_binv[m]  = __expf(-pb);
                }
            }
            __syncthreads();

            // attention weights w[b,s] + termination tap (one s per thread)
            {
                const int s = tid;  // NT == SS
                const int lb = lens[b];
                const float fs = (float)s;
                float aw = 0.0f, ar = 0.0f;
                #pragma unroll
                for (int m = 0; m < MM; ++m) {
                    const float binv = sh_binv[m];
                    const float z  = (fs - sh_ksi[m]) * binv;
                    const float hb = 0.5f * binv;
                    const float fr = sigf(z + hb);
                    const float fl = sigf(z - hb);
                    const float al = sh_alpha[m];
                    aw += al * (fr - fl);
                    ar += al * fr;
                }
                g_watt[b][s] = aw;
                out_align[((size_t)b * TT + t) * SS + s] = aw;
                if (t == TT - 1 && s == lb - 1) out_term[b] = 1.0f - ar;
            }
        }
        grid_barrier(++bgen);  // B2: h, w ready

        // ===================== ctx = w @ memory ============================
        {
            const int b  = bid >> 3;
            const int d0 = (bid & 7) * 128;
            const int w  = tid >> 5, lane = tid & 31;
            const float* mb = memv + (size_t)b * SS * DD + d0 + lane * 4;
            float4 acc = make_float4(0.f, 0.f, 0.f, 0.f);
            const int sbase = w * 32;
            #pragma unroll 4
            for (int si = 0; si < 32; ++si) {
                const int s = sbase + si;
                const float wv = g_watt[b][s];
                const float4 mv = *reinterpret_cast<const float4*>(mb + (size_t)s * DD);
                acc.x += wv * mv.x; acc.y += wv * mv.y;
                acc.z += wv * mv.z; acc.w += wv * mv.w;
            }
            float4* red = reinterpret_cast<float4*>(smem);
            red[w * 32 + lane] = acc;
            __syncthreads();
            if (tid < 32) {
                float4 r = red[tid];
                #pragma unroll
                for (int q = 1; q < 16; ++q) {
                    const float4 v = red[q * 32 + tid];
                    r.x += v.x; r.y += v.y; r.z += v.z; r.w += v.w;
                }
                const int di = d0 + tid * 4;
                *reinterpret_cast<float4*>(&g_ctx[b * DD + di]) = r;
                if (t == TT - 1)
                    *reinterpret_cast<float4*>(&out_ctx[b * DD + di]) = r;
            }
        }
        grid_barrier(++bgen);  // B3: ctx ready for next step's gates
    }
}

extern "C" void kernel_launch(void* const* d_in, const int* in_sizes, int n_in,
                              void* d_out, int out_size) {
    (void)in_sizes; (void)n_in; (void)out_size;
    const float* x_in  = (const float*)d_in[0];
    const float* memv  = (const float*)d_in[1];
    const int*   lens  = (const int*)  d_in[2];
    const float* W_ih  = (const float*)d_in[3];
    const float* W_hh  = (const float*)d_in[4];
    const float* b_ih  = (const float*)d_in[5];
    const float* b_hh  = (const float*)d_in[6];
    const float* Wg_w  = (const float*)d_in[7];
    const float* Wg_b  = (const float*)d_in[8];
    tts_kernel<<<NB, NT, 49152>>>(x_in, memv, lens, W_ih, W_hh,
                                  b_ih, b_hh, Wg_w, Wg_b, (float*)d_out);
}

// round 8
// speedup vs baseline: 1.7982x; 1.0880x over previous
#include <cuda_runtime.h>
#include <cstdint>

#define NB 128
#define NT 512
#define BB 16
#define TT 1024
#define DD 1024
#define SS 512
#define MM 16
#define KSPLIT 8
#define KBL 384                    // k per block
#define CBB 6176                   // bytes per cb staging region (6144 + pad)

// ---------------- persistent state (device globals; no allocation) ----------
__device__ float g_h[BB * DD];
__device__ float g_c[BB * DD];
__device__ float g_ctx[BB * DD];
__device__ float g_gpart[KSPLIT][BB][4 * DD];   // 2 MB
__device__ float g_watt[BB][SS];
__device__ unsigned g_count;
__device__ int g_flags[NB * 8];

__device__ __forceinline__ float sigf(float x) {
    return __fdividef(1.0f, 1.0f + __expf(-x));
}
__device__ __forceinline__ float tanhfast(float x) {
    const float xc = fminf(fmaxf(x, -15.0f), 15.0f);
    const float e  = __expf(2.0f * xc);
    return __fdividef(e - 1.0f, e + 1.0f);
}

// Grid barrier with distributed release. 128 blocks, single wave.
__device__ __forceinline__ void grid_barrier(int gen) {
    __syncthreads();
    if (threadIdx.x == 0) {
        __threadfence();
        const unsigned arrived = atomicAdd(&g_count, 1u);
        if (arrived == NB - 1) {
            g_count = 0u;
            __threadfence();
            #pragma unroll 8
            for (int i = 0; i < NB; ++i) g_flags[i * 8] = gen;
        } else {
            volatile int* f = &g_flags[blockIdx.x * 8];
            while (*f != gen) { __nanosleep(16); }
        }
        __threadfence();
    }
    __syncthreads();
}

extern __shared__ float smem[];

__device__ __forceinline__ uint32_t swz(uint32_t L) {
    return L ^ ((L >> 3) & 0x70u);
}

__global__ __launch_bounds__(NT, 1) void tts_kernel(
    const float* __restrict__ x_in,    // [B,T,D]
    const float* __restrict__ memv,    // [B,S,D]
    const int*   __restrict__ lens,    // [B]
    const float* __restrict__ W_ih,    // [4096,2048]
    const float* __restrict__ W_hh,    // [4096,1024]
    const float* __restrict__ b_ih,    // [4096]
    const float* __restrict__ b_hh,    // [4096]
    const float* __restrict__ Wg_w,    // [48,1024]
    const float* __restrict__ Wg_b,    // [48]
    float* __restrict__ out)
{
    const int bid = blockIdx.x;
    const int tid = threadIdx.x;

    // scratch placed after the 4*CBB staging area (phase-disjoint with it)
    float* sh_phi   = smem + 6176;   // 48
    float* sh_ksi   = smem + 6224;   // 16
    float* sh_binv  = smem + 6240;   // 16
    float* sh_alpha = smem + 6256;   // 16

    float* out_ctx   = out;
    float* out_align = out + BB * DD;
    float* out_term  = out + BB * DD + (size_t)BB * TT * SS;

    int bgen = 0;

    for (int i = bid * NT + tid; i < BB * DD; i += NB * NT) {
        g_h[i] = 0.0f; g_c[i] = 0.0f; g_ctx[i] = 0.0f;
    }
    grid_barrier(++bgen);

    // mapping: 16 j-tiles (256 j each) x 8 k-splits (384 k each)
    const int jt = bid >> 3;            // 0..15
    const int kb = bid & 7;             // 0..7
    const int kbase = kb * KBL;

    // thread: jg = tid>>4 (8 rows), lane4 = bg | ksl
    const int jg    = tid >> 4;         // 0..31
    const int lane4 = tid & 15;
    const int bg    = lane4 & 1;        // batches bg*8 .. bg*8+7
    const int ksl   = lane4 >> 1;       // 0..7; k-pairs kp = i*8+ksl
    const int j0    = jt * 256 + jg * 8;

    const float* wih = W_ih + (size_t)j0 * 2048;
    const float* whh = W_hh + (size_t)j0 * 1024;

    for (int t = 0; t < TT; ++t) {
        // ========== stage x slice [16 b x 384 k] (swizzled, float4 LDG) ====
        #pragma unroll
        for (int r = 0; r < 3; ++r) {
            const int qi = r * NT + tid;         // < 1536
            const int b  = qi / 96;
            const int kq = qi - b * 96;
            const int k  = kbase + kq * 4;
            float4 v;
            if (k < DD)
                v = *reinterpret_cast<const float4*>(&x_in[((size_t)b * TT + t) * DD + k]);
            else if (k < 2 * DD)
                v = *reinterpret_cast<const float4*>(&g_ctx[b * DD + (k - DD)]);
            else
                v = *reinterpret_cast<const float4*>(&g_h[b * DD + (k - 2 * DD)]);
            const int cb = b >> 2, bl = b & 3;
            char* base = reinterpret_cast<char*>(smem) + cb * CBB;
            const int kl = kq * 4;
            *reinterpret_cast<float*>(base + swz((uint32_t)((kl + 0) * 16 + bl * 4))) = v.x;
            *reinterpret_cast<float*>(base + swz((uint32_t)((kl + 1) * 16 + bl * 4))) = v.y;
            *reinterpret_cast<float*>(base + swz((uint32_t)((kl + 2) * 16 + bl * 4))) = v.z;
            *reinterpret_cast<float*>(base + swz((uint32_t)((kl + 3) * 16 + bl * 4))) = v.w;
        }
        __syncthreads();

        // ====== gates GEMM: 8 rows/thread, float2 weight double-buffer =====
        {
            unsigned long long acc[8][4];
            #pragma unroll
            for (int a = 0; a < 8; ++a)
                #pragma unroll
                for (int p = 0; p < 4; ++p) acc[a][p] = 0ull;

            float2 wA[8], wB[8];

            auto ldw = [&](float2* dst, int i) {
                const int k = kbase + (i * 8 + ksl) * 2;
                if (k < 2048) {
                    const float* p = wih + k;
                    #pragma unroll
                    for (int a = 0; a < 8; ++a)
                        dst[a] = *reinterpret_cast<const float2*>(p + (size_t)a * 2048);
                } else {
                    const float* p = whh + (k - 2048);
                    #pragma unroll
                    for (int a = 0; a < 8; ++a)
                        dst[a] = *reinterpret_cast<const float2*>(p + (size_t)a * 1024);
                }
            };

            const char* xb0 = reinterpret_cast<const char*>(smem) + (bg * 2) * CBB;

            auto compute = [&](const float2* w, int i) {
                const int kp = i * 8 + ksl;
                #pragma unroll
                for (int q = 0; q < 2; ++q) {
                    const int kl = kp * 2 + q;
                    const uint32_t L = swz((uint32_t)(kl * 16));
                    const double2 d0 = *reinterpret_cast<const double2*>(xb0 + L);
                    const double2 d1 = *reinterpret_cast<const double2*>(xb0 + CBB + L);
                    const unsigned long long xv0 = __double_as_longlong(d0.x);
                    const unsigned long long xv1 = __double_as_longlong(d0.y);
                    const unsigned long long xv2 = __double_as_longlong(d1.x);
                    const unsigned long long xv3 = __double_as_longlong(d1.y);
                    #pragma unroll
                    for (int a = 0; a < 8; ++a) {
                        const float wv = q ? w[a].y : w[a].x;
                        unsigned long long w2;
                        asm("mov.b64 %0, {%1, %1};" : "=l"(w2) : "r"(__float_as_uint(wv)));
                        asm("fma.rn.f32x2 %0, %1, %2, %0;" : "+l"(acc[a][0]) : "l"(w2), "l"(xv0));
                        asm("fma.rn.f32x2 %0, %1, %2, %0;" : "+l"(acc[a][1]) : "l"(w2), "l"(xv1));
                        asm("fma.rn.f32x2 %0, %1, %2, %0;" : "+l"(acc[a][2]) : "l"(w2), "l"(xv2));
                        asm("fma.rn.f32x2 %0, %1, %2, %0;" : "+l"(acc[a][3]) : "l"(w2), "l"(xv3));
                    }
                }
            };

            ldw(wA, 0);
            #pragma unroll 1
            for (int ii = 0; ii < 12; ++ii) {
                ldw(wB, 2 * ii + 1);
                compute(wA, 2 * ii);
                if (ii < 11) ldw(wA, 2 * ii + 2);
                compute(wB, 2 * ii + 1);
            }

            // reduce over ksl (lane bits 1-3): xor offsets 2,4,8
            #pragma unroll
            for (int off = 2; off <= 8; off <<= 1) {
                #pragma unroll
                for (int a = 0; a < 8; ++a)
                    #pragma unroll
                    for (int p = 0; p < 4; ++p) {
                        unsigned lo = (unsigned)acc[a][p];
                        unsigned hi = (unsigned)(acc[a][p] >> 32);
                        lo = __shfl_xor_sync(0xFFFFFFFFu, lo, off);
                        hi = __shfl_xor_sync(0xFFFFFFFFu, hi, off);
                        unsigned long long o = ((unsigned long long)hi << 32) | lo;
                        asm("add.rn.f32x2 %0, %0, %1;" : "+l"(acc[a][p]) : "l"(o));
                    }
            }

            // lane (bg,ksl) writes row a==ksl, its bg's 4 batch pairs
            #pragma unroll
            for (int a = 0; a < 8; ++a) {
                if (a == ksl) {
                    const int j = j0 + a;
                    #pragma unroll
                    for (int p = 0; p < 4; ++p) {
                        const int b0 = bg * 8 + 2 * p;
                        const unsigned long long v = acc[a][p];
                        g_gpart[kb][b0][j]     = __uint_as_float((unsigned)v);
                        g_gpart[kb][b0 + 1][j] = __uint_as_float((unsigned)(v >> 32));
                    }
                }
            }
        }
        grid_barrier(++bgen);  // B1: gates done

        // ============ LSTM + phi + GMM attention (blocks 0..15) ============
        if (bid < BB) {
            const int b = bid;
            #pragma unroll
            for (int r = 0; r < 2; ++r) {
                const int dd = r * NT + tid;
                float gi = b_ih[dd]          + b_hh[dd];
                float gf = b_ih[DD + dd]     + b_hh[DD + dd];
                float gg = b_ih[2 * DD + dd] + b_hh[2 * DD + dd];
                float go = b_ih[3 * DD + dd] + b_hh[3 * DD + dd];
                #pragma unroll
                for (int q = 0; q < KSPLIT; ++q) {
                    gi += g_gpart[q][b][dd];
                    gf += g_gpart[q][b][DD + dd];
                    gg += g_gpart[q][b][2 * DD + dd];
                    go += g_gpart[q][b][3 * DD + dd];
                }
                const float c = sigf(gf) * g_c[b * DD + dd] + sigf(gi) * tanhfast(gg);
                const float h = sigf(go) * tanhfast(c);
                g_c[b * DD + dd] = c;
                g_h[b * DD + dd] = h;
            }
            __syncthreads();

            // phi = h @ Wg_w^T + Wg_b
            {
                const int w = tid >> 5, lane = tid & 31;
                float hreg[32];
                #pragma unroll
                for (int i = 0; i < 32; ++i) hreg[i] = g_h[b * DD + i * 32 + lane];
                #pragma unroll
                for (int mi = 0; mi < 3; ++mi) {
                    const int mm = w * 3 + mi;
                    const float* wr = Wg_w + (size_t)mm * DD;
                    float acc = 0.0f;
                    #pragma unroll
                    for (int i = 0; i < 32; ++i) acc += wr[i * 32 + lane] * hreg[i];
                    #pragma unroll
                    for (int off = 16; off; off >>= 1)
                        acc += __shfl_xor_sync(0xFFFFFFFFu, acc, off);
                    if (lane == 0) sh_phi[mm] = acc + Wg_b[mm];
                }
            }
            __syncthreads();

            if (tid < 32) {
                const int m = tid & 15;
                const float pk = sh_phi[m];
                const float pb = sh_phi[MM + m];
                const float pa = sh_phi[2 * MM + m];
                float mx = pa;
                #pragma unroll
                for (int off = 1; off < 16; off <<= 1)
                    mx = fmaxf(mx, __shfl_xor_sync(0xFFFFFFFFu, mx, off, 16));
                const float e = __expf(pa - mx);
                float sum = e;
                #pragma unroll
                for (int off = 1; off < 16; off <<= 1)
                    sum += __shfl_xor_sync(0xFFFFFFFFu, sum, off, 16);
                if (tid < 16) {
                    sh_alpha[m] = e / sum;
                    sh_ksi[m]   = __expf(pk);
                    sh_binv[m]  = __expf(-pb);
                }
            }
            __syncthreads();

            {
                const int s = tid & (SS - 1);   // NT == SS
                const int lb = lens[b];
                const float fs = (float)s;
                float aw = 0.0f, ar = 0.0f;
                #pragma unroll
                for (int m = 0; m < MM; ++m) {
                    const float binv = sh_binv[m];
                    const float z  = (fs - sh_ksi[m]) * binv;
                    const float hb = 0.5f * binv;
                    const float fr = sigf(z + hb);
                    const float fl = sigf(z - hb);
                    const float al = sh_alpha[m];
                    aw += al * (fr - fl);
                    ar += al * fr;
                }
                g_watt[b][s] = aw;
                out_align[((size_t)b * TT + t) * SS + s] = aw;
                if (t == TT - 1 && s == lb - 1) out_term[b] = 1.0f - ar;
            }
        }
        grid_barrier(++bgen);  // B2: h, w ready

        // ===================== ctx = w @ memory ============================
        {
            const int b  = bid >> 3;
            const int d0 = (bid & 7) * 128;
            const int w  = tid >> 5, lane = tid & 31;
            const float* mb = memv + (size_t)b * SS * DD + d0 + lane * 4;
            float4 acc = make_float4(0.f, 0.f, 0.f, 0.f);
            const int sbase = w * 32;
            #pragma unroll 4
            for (int si = 0; si < 32; ++si) {
                const int s = sbase + si;
                const float wv = g_watt[b][s];
                const float4 mv = *reinterpret_cast<const float4*>(mb + (size_t)s * DD);
                acc.x += wv * mv.x; acc.y += wv * mv.y;
                acc.z += wv * mv.z; acc.w += wv * mv.w;
            }
            float4* red = reinterpret_cast<float4*>(smem);
            red[w * 32 + lane] = acc;
            __syncthreads();
            if (tid < 32) {
                float4 r = red[tid];
                #pragma unroll
                for (int q = 1; q < 16; ++q) {
                    const float4 v = red[q * 32 + tid];
                    r.x += v.x; r.y += v.y; r.z += v.z; r.w += v.w;
                }
                const int di = d0 + tid * 4;
                *reinterpret_cast<float4*>(&g_ctx[b * DD + di]) = r;
                if (t == TT - 1)
                    *reinterpret_cast<float4*>(&out_ctx[b * DD + di]) = r;
            }
        }
        grid_barrier(++bgen);  // B3: ctx ready
    }
}

extern "C" void kernel_launch(void* const* d_in, const int* in_sizes, int n_in,
                              void* d_out, int out_size) {
    (void)in_sizes; (void)n_in; (void)out_size;
    const float* x_in  = (const float*)d_in[0];
    const float* memv  = (const float*)d_in[1];
    const int*   lens  = (const int*)  d_in[2];
    const float* W_ih  = (const float*)d_in[3];
    const float* W_hh  = (const float*)d_in[4];
    const float* b_ih  = (const float*)d_in[5];
    const float* b_hh  = (const float*)d_in[6];
    const float* Wg_w  = (const float*)d_in[7];
    const float* Wg_b  = (const float*)d_in[8];
    tts_kernel<<<NB, NT, 28672>>>(x_in, memv, lens, W_ih, W_hh,
                                  b_ih, b_hh, Wg_w, Wg_b, (float*)d_out);
}